// round 5
// baseline (speedup 1.0000x reference)
#include <cuda_runtime.h>
#include <cuda_bf16.h>
#include <math.h>
#include <cstdint>

// Model dims
#define NL 32
#define D  256
#define DI 512
#define NS 16
#define RR 16
#define KC 4
#define VV 4096
#define FF 1024
#define BB 32
#define LL 256
#define TT (BB*LL)

// ---------------- scratch ----------------------------------------------------
__device__ float g_x  [TT * D];
__device__ float g_h  [TT * D];
__device__ float g_xz [TT * 2 * DI];
__device__ float g_xc [TT * DI];
__device__ float g_dbc[TT * 48];
__device__ float g_dt [TT * DI];
__device__ float g_y  [TT * DI];
__device__ float g_h1 [TT * FF];

// ---------------- packed f32x2 helpers ---------------------------------------
#define FMA2(acc, a, b) \
    asm("fma.rn.f32x2 %0, %1, %2, %0;" : "+l"(acc) : "l"(a), "l"(b))
#define UNPACK2(lo, hi, v) \
    asm("mov.b64 {%0, %1}, %2;" : "=r"(lo), "=r"(hi) : "l"(v))

// ---------------- FFMA2 NT GEMM ----------------------------------------------
// C[m][n] = dot(A[m,:], B[n,:]) + epilogue
// A: M x K (lda), B: N x K (ldb), C: M x ldc.
// Accumulator pairs run along N: acc[i][j] = {C[m0+i][n0+2j], C[m0+i][n0+2j+1]}
// A values are stored DUPLICATED in smem ({a,a}) so the mainloop needs no movs.
// EPI: 0 plain, 1 bias+relu, 2 bias, 3 residual add, 4 bias+softplus
#define GBN 64
#define GBK 16

template<int EPI, int TBM>
__global__ __launch_bounds__(256, 2)
void gemm2(const float* __restrict__ A, int lda,
           const float* __restrict__ B, int ldb,
           float* __restrict__ C, int ldc,
           const float* __restrict__ bias,
           const float* __restrict__ res,
           int N, int K)
{
    constexpr int MR  = TBM / 16;        // rows per thread (8 or 4)
    constexpr int AH  = TBM / 64;        // float4s per thread for A tile (2 or 1)
    constexpr int ADW = 2 * TBM + 4;     // padded duplicated-A row (floats)
    constexpr int BSW = GBN + 4;         // padded B row (floats)

    __shared__ float Ad[2][GBK][ADW];
    __shared__ float Bs[2][GBK][BSW];

    int tid = threadIdx.x;
    int bm = blockIdx.y * TBM, bn = blockIdx.x * GBN;
    int tx = tid & 15, ty = tid >> 4;
    int m0 = ty * MR, n0 = tx * 4;

    int lr = tid >> 2;            // 0..63
    int lk = (tid & 3) * 4;       // k sub-chunk

    unsigned long long acc[MR][2];
    #pragma unroll
    for (int i = 0; i < MR; i++) { acc[i][0] = 0ull; acc[i][1] = 0ull; }

    float4 pa[AH], pb;

    auto fetch = [&](int k0) {
        #pragma unroll
        for (int h = 0; h < AH; h++)
            pa[h] = *reinterpret_cast<const float4*>(
                A + (size_t)(bm + lr + h * 64) * lda + k0 + lk);
        pb = make_float4(0.f, 0.f, 0.f, 0.f);
        if (bn + lr < N)
            pb = *reinterpret_cast<const float4*>(
                B + (size_t)(bn + lr) * ldb + k0 + lk);
    };
    auto stage = [&](int buf) {
        #pragma unroll
        for (int h = 0; h < AH; h++) {
            int r2 = 2 * (lr + h * 64);
            float va[4] = {pa[h].x, pa[h].y, pa[h].z, pa[h].w};
            #pragma unroll
            for (int j = 0; j < 4; j++)
                *reinterpret_cast<float2*>(&Ad[buf][lk + j][r2]) =
                    make_float2(va[j], va[j]);
        }
        Bs[buf][lk + 0][lr] = pb.x;
        Bs[buf][lk + 1][lr] = pb.y;
        Bs[buf][lk + 2][lr] = pb.z;
        Bs[buf][lk + 3][lr] = pb.w;
    };

    int NC = K / GBK;
    fetch(0);
    stage(0);
    __syncthreads();

    for (int kc = 0; kc < NC; kc++) {
        int buf = kc & 1;
        if (kc + 1 < NC) fetch((kc + 1) * GBK);

        #pragma unroll
        for (int k = 0; k < GBK; k++) {
            // duplicated a pairs: ulonglong2 gives {dup(a_m), dup(a_m+1)}
            unsigned long long ad[MR];
            #pragma unroll
            for (int i = 0; i < MR; i += 2) {
                ulonglong2 q = *reinterpret_cast<const ulonglong2*>(
                    &Ad[buf][k][2 * (m0 + i)]);
                ad[i] = q.x; ad[i + 1] = q.y;
            }
            ulonglong2 bq = *reinterpret_cast<const ulonglong2*>(
                &Bs[buf][k][n0]);
            #pragma unroll
            for (int i = 0; i < MR; i++) {
                FMA2(acc[i][0], ad[i], bq.x);
                FMA2(acc[i][1], ad[i], bq.y);
            }
        }

        if (kc + 1 < NC) {
            stage(buf ^ 1);
            __syncthreads();
        }
    }

    // ---- epilogue (pairs along N -> contiguous float4 stores)
    if (bn + n0 >= N) return;
    #pragma unroll
    for (int i = 0; i < MR; i++) {
        int row = bm + m0 + i;
        unsigned u0, u1, u2, u3;
        UNPACK2(u0, u1, acc[i][0]);
        UNPACK2(u2, u3, acc[i][1]);
        float v[4] = {__uint_as_float(u0), __uint_as_float(u1),
                      __uint_as_float(u2), __uint_as_float(u3)};
        if (EPI == 1 || EPI == 2 || EPI == 4) {
            #pragma unroll
            for (int j = 0; j < 4; j++) v[j] += bias[bn + n0 + j];
            if (EPI == 1) {
                #pragma unroll
                for (int j = 0; j < 4; j++) v[j] = fmaxf(v[j], 0.f);
            } else if (EPI == 4) {
                #pragma unroll
                for (int j = 0; j < 4; j++)
                    v[j] = (v[j] > 20.f) ? v[j] : log1pf(expf(v[j]));
            }
        }
        size_t o = (size_t)row * ldc + bn + n0;
        if (EPI == 3) {
            float4 r4 = *reinterpret_cast<const float4*>(res + o);
            v[0] += r4.x; v[1] += r4.y; v[2] += r4.z; v[3] += r4.w;
        }
        *reinterpret_cast<float4*>(C + o) = make_float4(v[0], v[1], v[2], v[3]);
    }
}

// ---------------- embedding --------------------------------------------------
__global__ void embed_kernel(const int* __restrict__ tok,
                             const float* __restrict__ emb,
                             float* __restrict__ x)
{
    int t = blockIdx.x, d = threadIdx.x;
    x[t * D + d] = emb[(size_t)tok[t] * D + d];
}

// ---------------- layernorm --------------------------------------------------
__global__ void ln_kernel(const float* __restrict__ x,
                          const float* __restrict__ w,
                          const float* __restrict__ b,
                          float* __restrict__ h)
{
    int t = blockIdx.x, d = threadIdx.x;
    float v = x[t * D + d];
    float s = v, s2 = v * v;
    #pragma unroll
    for (int o = 16; o > 0; o >>= 1) {
        s  += __shfl_xor_sync(0xffffffffu, s,  o);
        s2 += __shfl_xor_sync(0xffffffffu, s2, o);
    }
    __shared__ float ws[8], ws2[8];
    int wi = d >> 5;
    if ((d & 31) == 0) { ws[wi] = s; ws2[wi] = s2; }
    __syncthreads();
    if (d < 32) {
        float a  = (d < 8) ? ws[d]  : 0.f;
        float a2 = (d < 8) ? ws2[d] : 0.f;
        #pragma unroll
        for (int o = 4; o > 0; o >>= 1) {
            a  += __shfl_xor_sync(0xffffffffu, a,  o);
            a2 += __shfl_xor_sync(0xffffffffu, a2, o);
        }
        if (d == 0) { ws[0] = a; ws2[0] = a2; }
    }
    __syncthreads();
    float mu  = ws[0] * (1.f / D);
    float var = ws2[0] * (1.f / D) - mu * mu;
    float inv = rsqrtf(var + 1e-5f);
    h[t * D + d] = (v - mu) * inv * w[d] + b[d];
}

// ---------------- causal depthwise conv1d + SiLU ----------------------------
__global__ void conv_kernel(const float* __restrict__ xz,
                            const float* __restrict__ cw,
                            const float* __restrict__ cb,
                            float* __restrict__ xc)
{
    int t = blockIdx.x;
    int e = blockIdx.y * 256 + threadIdx.x;
    int l = t & (LL - 1);
    float acc = cb[e];
    #pragma unroll
    for (int k = 0; k < KC; k++) {
        int ll = l - (KC - 1) + k;
        if (ll >= 0)
            acc = fmaf(xz[(size_t)(t - (KC - 1) + k) * (2 * DI) + e], cw[e * KC + k], acc);
    }
    float s = 1.f / (1.f + __expf(-acc));
    xc[(size_t)t * DI + e] = acc * s;
}

// ---------------- selective scan + skip + gate ------------------------------
__global__ void scan_kernel(const float* __restrict__ dbc,
                            const float* __restrict__ dtf,
                            const float* __restrict__ xc,
                            const float* __restrict__ xz,
                            const float* __restrict__ A_log,
                            const float* __restrict__ Dskip,
                            float* __restrict__ y)
{
    int b = blockIdx.y;
    int tid = threadIdx.x;
    int e = blockIdx.x * 128 + tid;
    __shared__ float sB[8][NS], sC[8][NS];

    float A[NS], h[NS];
    #pragma unroll
    for (int n = 0; n < NS; n++) {
        A[n] = -__expf(A_log[e * NS + n]);
        h[n] = 0.f;
    }
    float Ds = Dskip[e];

    for (int g = 0; g < LL / 8; g++) {
        __syncthreads();
        #pragma unroll
        for (int i = 0; i < 2; i++) {
            int id = tid + i * 128;
            int st = id >> 5, j = id & 31;
            int t = b * LL + g * 8 + st;
            float v = dbc[(size_t)t * 48 + RR + j];
            if (j < NS) sB[st][j] = v;
            else        sC[st][j - NS] = v;
        }
        __syncthreads();
        #pragma unroll
        for (int s = 0; s < 8; s++) {
            int t = b * LL + g * 8 + s;
            float dtv = dtf[(size_t)t * DI + e];
            float xv  = xc[(size_t)t * DI + e];
            float du  = dtv * xv;
            float acc = 0.f;
            #pragma unroll
            for (int n = 0; n < NS; n++) {
                float dA = __expf(dtv * A[n]);
                h[n] = fmaf(h[n], dA, du * sB[s][n]);
                acc = fmaf(h[n], sC[s][n], acc);
            }
            float zv = xz[(size_t)t * (2 * DI) + DI + e];
            float sig = 1.f / (1.f + __expf(-zv));
            y[(size_t)t * DI + e] = (acc + xv * Ds) * (zv * sig);
        }
    }
}

// ---------------- host side --------------------------------------------------
extern "C" void kernel_launch(void* const* d_in, const int* in_sizes, int n_in,
                              void* d_out, int out_size)
{
    const int*   tok    = (const int*)  d_in[0];
    const float* emb    = (const float*)d_in[1];
    const float* ln_w   = (const float*)d_in[2];
    const float* ln_b   = (const float*)d_in[3];
    const float* in_w   = (const float*)d_in[4];
    const float* conv_w = (const float*)d_in[5];
    const float* conv_b = (const float*)d_in[6];
    const float* xp_w   = (const float*)d_in[7];
    const float* dt_w   = (const float*)d_in[8];
    const float* dt_b   = (const float*)d_in[9];
    const float* A_log  = (const float*)d_in[10];
    const float* Dskip  = (const float*)d_in[11];
    const float* out_w  = (const float*)d_in[12];
    const float* W1     = (const float*)d_in[13];
    const float* b1     = (const float*)d_in[14];
    const float* W2     = (const float*)d_in[15];
    const float* b2     = (const float*)d_in[16];
    float* out = (float*)d_out;

    float *px, *ph, *pxz, *pxc, *pdbc, *pdt, *py, *ph1;
    cudaGetSymbolAddress((void**)&px,   g_x);
    cudaGetSymbolAddress((void**)&ph,   g_h);
    cudaGetSymbolAddress((void**)&pxz,  g_xz);
    cudaGetSymbolAddress((void**)&pxc,  g_xc);
    cudaGetSymbolAddress((void**)&pdbc, g_dbc);
    cudaGetSymbolAddress((void**)&pdt,  g_dt);
    cudaGetSymbolAddress((void**)&py,   g_y);
    cudaGetSymbolAddress((void**)&ph1,  g_h1);

    embed_kernel<<<TT, D>>>(tok, emb, px);

    for (int l = 0; l < NL; l++) {
        const float* lw  = ln_w   + (size_t)l * D;
        const float* lb  = ln_b   + (size_t)l * D;
        const float* iw  = in_w   + (size_t)l * 2 * DI * D;
        const float* cw  = conv_w + (size_t)l * DI * KC;
        const float* cb  = conv_b + (size_t)l * DI;
        const float* xw  = xp_w   + (size_t)l * 48 * DI;
        const float* dw  = dt_w   + (size_t)l * DI * RR;
        const float* db  = dt_b   + (size_t)l * DI;
        const float* al  = A_log  + (size_t)l * DI * NS;
        const float* ds  = Dskip  + (size_t)l * DI;
        const float* ow  = out_w  + (size_t)l * D * DI;

        ln_kernel<<<TT, D>>>(px, lw, lb, ph);

        // xz = LN(x) @ in_w^T   (8192 x 1024 x 256)
        gemm2<0,128><<<dim3((2 * DI) / GBN, TT / 128), 256>>>(
            ph, D, iw, D, pxz, 2 * DI, nullptr, nullptr, 2 * DI, D);

        conv_kernel<<<dim3(TT, 2), 256>>>(pxz, cw, cb, pxc);

        // dbc = xc @ xp_w^T   (8192 x 48 x 512)  -- TBM=64 for 128 blocks
        gemm2<0,64><<<dim3(1, TT / 64), 256>>>(
            pxc, DI, xw, DI, pdbc, 48, nullptr, nullptr, 48, DI);

        // dt = softplus(dbc[:, :16] @ dt_w^T + dt_b)   (8192 x 512 x 16)
        gemm2<4,128><<<dim3(DI / GBN, TT / 128), 256>>>(
            pdbc, 48, dw, RR, pdt, DI, db, nullptr, DI, RR);

        scan_kernel<<<dim3(4, BB), 128>>>(pdbc, pdt, pxc, pxz, al, ds, py);

        // x += y @ out_w^T   (8192 x 256 x 512)
        gemm2<3,128><<<dim3(D / GBN, TT / 128), 256>>>(
            py, DI, ow, DI, px, D, nullptr, px, D, DI);
    }

    // head
    gemm2<1,128><<<dim3(FF / GBN, TT / 128), 256>>>(
        px, D, W1, D, ph1, FF, b1, nullptr, FF, D);
    gemm2<2,128><<<dim3(VV / GBN, TT / 128), 256>>>(
        ph1, FF, W2, FF, out, VV, b2, nullptr, VV, FF);
}